// round 12
// baseline (speedup 1.0000x reference)
#include <cuda_runtime.h>
#include <cuda_pipeline.h>
#include <math.h>

#define NIMG 4
#define NCLS 19
#define HWPIX 589824            // 768*768
#define NTOT (NIMG * HWPIX)
#define IGN 255
#define EDGE_T 0.8f
#define PPT 4                   // pixels per thread
#define TPB 256
#define BPI (HWPIX / (TPB * PPT))   // 576 blocks per image
#define GRID (NIMG * BPI)           // 2304
#define INVC 31                 // "invalid" class sentinel -> absorber slot 31
#define PDEPTH 6                // cp.async prefetch depth (channels)

// ---------------- device-global scratch (no allocations allowed) ----------------
__device__ double g_seg_sum[NIMG * NCLS];
__device__ double g_att_sum[NIMG * NCLS];
__device__ int    g_seg_cnt[NIMG * NCLS];
__device__ int    g_att_cnt[NIMG * NCLS];
__device__ double g_bce_pos, g_bce_neg;
__device__ int    g_pos, g_neg;
__device__ unsigned g_done;

// ---------------- single fused kernel ----------------
// cp.async SMEM ring keeps DRAM saturated; epilogue uses per-block shared
// atomics (32-slot class arrays) instead of the 19-class shuffle reduction
// that was eating ~630 issue slots/warp in R10.
__global__ void __launch_bounds__(TPB) k_fused(const float* __restrict__ segin,
                                               const float* __restrict__ edgein,
                                               const int* __restrict__ segmask,
                                               const int* __restrict__ emask,
                                               float* __restrict__ out) {
    __shared__ float4 pbuf[PDEPTH][TPB];     // 24 KB prefetch ring (per-thread slots)
    __shared__ float  sh_ss[32];             // per-class nll sum   (slot 31 = ignored)
    __shared__ float  sh_sa[32];             // per-class att nll sum
    __shared__ int    sh_cc[32];             // seg cnt lo16 | att cnt hi16
    __shared__ float  sh_bp, sh_bn;          // bce pos/neg
    __shared__ int    sh_pn;                 // pos lo16 | neg hi16

    int n   = blockIdx.x / BPI;
    int tid = threadIdx.x;

    int local = (blockIdx.x % BPI) * (TPB * PPT) + tid * PPT;
    int p     = n * HWPIX + local;

    const float* sp = segin + (size_t)n * (size_t)NCLS * (size_t)HWPIX + (size_t)local;

    // kick off the segin pipeline FIRST so DRAM is busy during the prologue
#pragma unroll
    for (int c = 0; c < PDEPTH; c++) {
        __pipeline_memcpy_async(&pbuf[c][tid], sp + (size_t)c * HWPIX, 16);
        __pipeline_commit();
    }

    // zero the block accumulators while loads fly
    if (tid < 32) { sh_ss[tid] = 0.f; sh_sa[tid] = 0.f; sh_cc[tid] = 0; }
    if (tid == 32) { sh_bp = 0.f; sh_bn = 0.f; sh_pn = 0; }

    // ---- prologue: masks + BCE ----
    int4   t4 = *(const int4*)(segmask + p);
    float4 e4 = *(const float4*)(edgein + p);
    int4   m4 = *(const int4*)(emask + p);

    int   tv[PPT] = {t4.x, t4.y, t4.z, t4.w};
    float ev[PPT] = {e4.x, e4.y, e4.z, e4.w};
    int   mv[PPT] = {m4.x, m4.y, m4.z, m4.w};

    int tcls[PPT];               // class for select; INVC for ignored pixels
    unsigned attb = 0u;
    float bce_p = 0.f, bce_n = 0.f;
    unsigned pn = 0;             // pos lo16, neg hi16
#pragma unroll
    for (int i = 0; i < PPT; i++) {
        bool v  = (tv[i] != IGN);
        tcls[i] = v ? min(max(tv[i], 0), NCLS - 1) : INVC;
        if (v && (ev[i] > EDGE_T)) attb |= (1u << i);

        float xx = ev[i];
        float b  = fmaxf(xx, 0.f) - xx * (float)mv[i] + log1pf(__expf(-fabsf(xx)));
        if (mv[i] == 1) { bce_p += b; pn += 1u; }
        else if (mv[i] == 0) { bce_n += b; pn += 0x10000u; }
    }

    __syncthreads();   // accumulators zeroed before any atomic below

    // ---- channel sweep out of the SMEM ring ----
    float s[PPT], xt[PPT];
#pragma unroll
    for (int i = 0; i < PPT; i++) { s[i] = 0.f; xt[i] = 0.f; }

#pragma unroll
    for (int c = 0; c < NCLS; c++) {
        __pipeline_wait_prior(PDEPTH - 1);        // channel c's copy has landed
        float4 x = pbuf[c % PDEPTH][tid];
        int cn = c + PDEPTH;
        if (cn < NCLS)
            __pipeline_memcpy_async(&pbuf[c % PDEPTH][tid], sp + (size_t)cn * HWPIX, 16);
        __pipeline_commit();                      // keep group numbering uniform

        float xv[PPT] = {x.x, x.y, x.z, x.w};
#pragma unroll
        for (int i = 0; i < PPT; i++) {
            s[i] += __expf(xv[i]);
            xt[i] = (c == tcls[i]) ? xv[i] : xt[i];
        }
    }

    // ---- per-pixel nll -> shared atomics (slot 31 absorbs ignored) ----
#pragma unroll
    for (int i = 0; i < PPT; i++) {
        float nll = __logf(s[i]) - xt[i];        // -log_softmax[target]
        bool  a   = (attb >> i) & 1u;
        atomicAdd(&sh_ss[tcls[i]], nll);
        if (a) atomicAdd(&sh_sa[tcls[i]], nll);
        atomicAdd(&sh_cc[tcls[i]], a ? 0x10001 : 1);
    }
    atomicAdd(&sh_bp, bce_p);
    atomicAdd(&sh_bn, bce_n);
    atomicAdd(&sh_pn, (int)pn);
    __syncthreads();

    // ---- block -> global accumulation ----
    if (tid < NCLS) {
        int gi = n * NCLS + tid;
        int cc = sh_cc[tid];
        atomicAdd(&g_seg_sum[gi], (double)sh_ss[tid]);
        atomicAdd(&g_att_sum[gi], (double)sh_sa[tid]);
        atomicAdd(&g_seg_cnt[gi], cc & 0xffff);
        atomicAdd(&g_att_cnt[gi], cc >> 16);
    } else if (tid == 32) {
        atomicAdd(&g_bce_pos, (double)sh_bp);
        atomicAdd(&g_bce_neg, (double)sh_bn);
        int c = sh_pn;
        atomicAdd(&g_pos, c & 0xffff);
        atomicAdd(&g_neg, ((unsigned)c) >> 16);
    }

    // ---- fan-in: last block finalizes ----
    __syncthreads();
    __shared__ unsigned s_last;
    if (tid == 0) {
        __threadfence();
        s_last = (atomicAdd(&g_done, 1u) == GRID - 1u);
    }
    __syncthreads();
    if (!s_last) return;
    __threadfence();   // acquire: make all blocks' g_* writes visible

    // ---------------- finalize (parallel, division-light) ----------------
    __shared__ double f_ss[NIMG * NCLS], f_as[NIMG * NCLS];
    __shared__ int    f_sc[NIMG * NCLS], f_ac[NIMG * NCLS];
    __shared__ double f_rs[NIMG], f_ra[NIMG];
    __shared__ double f_t[NIMG * NCLS][4];
    __shared__ double f_img[NIMG][2];
    __shared__ double f_bce[2];
    __shared__ int    f_pn[2];

    if (tid < NIMG * NCLS) {
        f_ss[tid] = g_seg_sum[tid];
        f_as[tid] = g_att_sum[tid];
        f_sc[tid] = g_seg_cnt[tid];
        f_ac[tid] = g_att_cnt[tid];
    }
    if (tid == 96) { f_bce[0] = g_bce_pos; f_bce[1] = g_bce_neg; }
    if (tid == 97) { f_pn[0] = g_pos; f_pn[1] = g_neg; }
    __syncthreads();

    if (tid < NIMG) {
        int ssum = 0, asum = 0;
#pragma unroll
        for (int c = 0; c < NCLS; c++) { ssum += f_sc[tid * NCLS + c]; asum += f_ac[tid * NCLS + c]; }
        f_rs[tid] = 1.0 / (double)ssum;
        f_ra[tid] = 1.0 / (double)asum;
    }
    __syncthreads();

    if (tid < NIMG * NCLS) {
        int nimg = tid / NCLS;
        int sc = f_sc[tid], ac = f_ac[tid];
        double ws = sc ? (2.0 - (double)sc * f_rs[nimg]) : 1.0;
        double wa = ac ? (2.0 - (double)ac * f_ra[nimg]) : 1.0;
        f_t[tid][0] = ws * f_ss[tid];
        f_t[tid][1] = ws * (double)sc;
        f_t[tid][2] = wa * f_as[tid];
        f_t[tid][3] = wa * (double)ac;
    }
    __syncthreads();

    if (tid < NIMG) {
        double sn = 0, sd = 0, an = 0, ad = 0;
#pragma unroll
        for (int c = 0; c < NCLS; c++) {
            sn += f_t[tid * NCLS + c][0]; sd += f_t[tid * NCLS + c][1];
            an += f_t[tid * NCLS + c][2]; ad += f_t[tid * NCLS + c][3];
        }
        f_img[tid][0] = sn / sd;
        f_img[tid][1] = an / ad;
    }
    __syncthreads();

    if (tid == 0) {
        double segl = 0.0, attl = 0.0;
#pragma unroll
        for (int nn2 = 0; nn2 < NIMG; nn2++) { segl += f_img[nn2][0]; attl += f_img[nn2][1]; }
        double pp = (double)f_pn[0], nng = (double)f_pn[1], sm = pp + nng;
        double bce = ((nng / sm) * f_bce[0] + (pp / sm) * f_bce[1]) / (double)NTOT;
        out[0] = (float)(segl + 0.3 * bce + 0.1 * attl);
    }

    // reset scratch for next graph replay
    if (tid < NIMG * NCLS) {
        g_seg_sum[tid] = 0.0; g_att_sum[tid] = 0.0;
        g_seg_cnt[tid] = 0;   g_att_cnt[tid] = 0;
    }
    if (tid == 96) { g_bce_pos = 0.0; g_bce_neg = 0.0; }
    if (tid == 97) { g_pos = 0; g_neg = 0; }
    if (tid == 98) g_done = 0u;
}

extern "C" void kernel_launch(void* const* d_in, const int* in_sizes, int n_in,
                              void* d_out, int out_size) {
    const float* segin   = (const float*)d_in[0];
    const float* edgein  = (const float*)d_in[1];
    const int*   segmask = (const int*)d_in[2];
    const int*   emask   = (const int*)d_in[3];

    k_fused<<<GRID, TPB>>>(segin, edgein, segmask, emask, (float*)d_out);
}